// round 2
// baseline (speedup 1.0000x reference)
#include <cuda_runtime.h>
#include <cstdint>

// Problem constants
#define E_  8
#define T_  2048
#define H_  2880
#define D_  2880
#define N2_ 5760   // 2*D

// Tiling
constexpr int BM = 128, BN = 96, BK = 32;
constexpr int LDA = BK + 4;    // 36  (smem A row stride, floats)
constexpr int LDB = BN + 4;    // 100 (smem B row stride)
constexpr int LDC = BN + 4;    // 100 (smem C row stride)
constexpr int AS_SZ = BM * LDA;        // 4608 floats
constexpr int BS_SZ = BK * LDB;        // 3200 floats
constexpr int SMEM_BYTES = (2 * AS_SZ + 2 * BS_SZ) * 4;  // 62464 B (C tile aliases: 51200 B)

// Scratch: routing-scaled activated hidden states, [E][T][D] fp32 (189 MB)
__device__ float g_hidden[(long long)E_ * T_ * D_];

// ---------------- low-level helpers ----------------
__device__ __forceinline__ unsigned smem_u32(const void* p) {
    return (unsigned)__cvta_generic_to_shared(p);
}
__device__ __forceinline__ void cp16(float* s, const float* g) {
    asm volatile("cp.async.cg.shared.global [%0], [%1], 16;" :: "r"(smem_u32(s)), "l"(g));
}
__device__ __forceinline__ void cp_commit() { asm volatile("cp.async.commit_group;"); }
__device__ __forceinline__ void cp_wait1()  { asm volatile("cp.async.wait_group 1;"); }
__device__ __forceinline__ void cp_wait0()  { asm volatile("cp.async.wait_group 0;"); }

__device__ __forceinline__ uint32_t f2tf32(float x) {
    uint32_t r; asm("cvt.rna.tf32.f32 %0, %1;" : "=r"(r) : "f"(x)); return r;
}
__device__ __forceinline__ void mma8(float* c, const uint32_t* a, const uint32_t* b) {
    asm volatile("mma.sync.aligned.m16n8k8.row.col.f32.tf32.tf32.f32 "
        "{%0,%1,%2,%3}, {%4,%5,%6,%7}, {%8,%9}, {%0,%1,%2,%3};"
        : "+f"(c[0]), "+f"(c[1]), "+f"(c[2]), "+f"(c[3])
        : "r"(a[0]), "r"(a[1]), "r"(a[2]), "r"(a[3]), "r"(b[0]), "r"(b[1]));
}

// ---------------- tile loads (cp.async, 16B chunks, no bounds checks: all dims divide) ----
__device__ __forceinline__ void load_A(float* As, const float* Ag, int lda, int tid) {
#pragma unroll
    for (int i = 0; i < 4; i++) {
        int c = tid + i * 256;
        int r = c >> 3, q = (c & 7) << 2;       // 128 rows x 8 chunks
        cp16(As + r * LDA + q, Ag + (long long)r * lda + q);
    }
}
__device__ __forceinline__ void load_B(float* Bs, const float* Bg, int ldb, int tid) {
#pragma unroll
    for (int i = 0; i < 3; i++) {
        int c = tid + i * 256;
        int r = c / 24, q = (c % 24) << 2;      // 32 rows x 24 chunks
        cp16(Bs + r * LDB + q, Bg + (long long)r * ldb + q);
    }
}

// ---------------- per-stage compute: warp tile 32x48, m16n8k8 tf32 ----------------
__device__ __forceinline__ void compute_stage(const float* As, const float* Bs,
                                               float (&acc)[2][6][4],
                                               int wm, int wn, int lane) {
    const int ra = lane >> 2;     // 0..7
    const int ca = lane & 3;      // 0..3
#pragma unroll
    for (int ks = 0; ks < 4; ks++) {
        const int k0 = ks * 8;
        uint32_t a[2][4], b[6][2];
#pragma unroll
        for (int i = 0; i < 2; i++) {
            const float* ap = As + (wm * 32 + i * 16 + ra) * LDA + k0 + ca;
            a[i][0] = f2tf32(ap[0]);
            a[i][1] = f2tf32(ap[8 * LDA]);
            a[i][2] = f2tf32(ap[4]);
            a[i][3] = f2tf32(ap[8 * LDA + 4]);
        }
#pragma unroll
        for (int j = 0; j < 6; j++) {
            const float* bp = Bs + (k0 + ca) * LDB + wn * 48 + j * 8 + ra;
            b[j][0] = f2tf32(bp[0]);
            b[j][1] = f2tf32(bp[4 * LDB]);
        }
#pragma unroll
        for (int i = 0; i < 2; i++)
#pragma unroll
            for (int j = 0; j < 6; j++)
                mma8(acc[i][j], a[i], b[j]);
    }
}

__device__ __forceinline__ void store_acc(float* Cs, const float (&acc)[2][6][4],
                                          int wm, int wn, int lane) {
    const int r0 = lane >> 2, c0 = 2 * (lane & 3);
#pragma unroll
    for (int i = 0; i < 2; i++)
#pragma unroll
        for (int j = 0; j < 6; j++) {
            float* p = Cs + (wm * 32 + i * 16 + r0) * LDC + wn * 48 + j * 8 + c0;
            p[0] = acc[i][j][0];
            p[1] = acc[i][j][1];
            p[8 * LDC]     = acc[i][j][2];
            p[8 * LDC + 1] = acc[i][j][3];
        }
}

// ================= Kernel 1: gate_up GEMM + bias + interleaved GLU + routing scale ====
__global__ void __launch_bounds__(256, 2)
k_gateup(const float* __restrict__ x, const float* __restrict__ w1,
         const float* __restrict__ b1, const float* __restrict__ routing) {
    extern __shared__ float sm[];
    float* Asb[2] = { sm, sm + AS_SZ };
    float* Bsb[2] = { sm + 2 * AS_SZ, sm + 2 * AS_SZ + BS_SZ };
    float* Cs = sm;

    const int tid = threadIdx.x, lane = tid & 31, warp = tid >> 5;
    const int wm = warp & 3, wn = warp >> 2;
    const int n0 = blockIdx.x * BN;           // gate_up column base (even)
    const int t0 = blockIdx.y * BM;
    const int e  = blockIdx.z;

    const float* Abase = x + (long long)t0 * H_;
    const float* Bbase = w1 + (long long)e * H_ * N2_ + n0;

    float acc[2][6][4];
#pragma unroll
    for (int i = 0; i < 2; i++)
#pragma unroll
        for (int j = 0; j < 6; j++)
#pragma unroll
            for (int q = 0; q < 4; q++) acc[i][j][q] = 0.f;

    constexpr int KT = H_ / BK;  // 90
    load_A(Asb[0], Abase, H_, tid);
    load_B(Bsb[0], Bbase, N2_, tid);
    cp_commit();

    for (int kt = 0; kt < KT; kt++) {
        const int nkt = kt + 1;
        if (nkt < KT) {
            load_A(Asb[nkt & 1], Abase + nkt * BK, H_, tid);
            load_B(Bsb[nkt & 1], Bbase + (long long)nkt * BK * N2_, N2_, tid);
            cp_commit();
            cp_wait1();
        } else {
            cp_wait0();
        }
        __syncthreads();
        compute_stage(Asb[kt & 1], Bsb[kt & 1], acc, wm, wn, lane);
        __syncthreads();
    }

    store_acc(Cs, acc, wm, wn, lane);
    __syncthreads();

    // epilogue: bias + interleaved GLU (even=gate, odd=up), scale by routing weight
    const float* brow = b1 + e * N2_ + n0;
    const int j0 = n0 >> 1;
    for (int idx = tid; idx < BM * 48; idx += 256) {
        const int r = idx / 48, m = idx % 48;
        float gate = Cs[r * LDC + 2 * m]     + brow[2 * m];
        float up   = Cs[r * LDC + 2 * m + 1] + brow[2 * m + 1];
        gate = fminf(gate, 7.0f);
        up   = fminf(fmaxf(up, -7.0f), 7.0f);
        const float glu = gate / (1.0f + __expf(-1.702f * gate));
        const float hv  = (up + 1.0f) * glu;
        const int t = t0 + r;
        g_hidden[((long long)e * T_ + t) * D_ + j0 + m] = hv * routing[t * E_ + e];
    }
}

// ================= Kernel 2: flat GEMM over K = E*D, epilogue adds routed down-bias ====
__global__ void __launch_bounds__(256, 2)
k_down(const float* __restrict__ w2, const float* __restrict__ b2,
       const float* __restrict__ routing, float* __restrict__ out) {
    extern __shared__ float sm[];
    float* Asb[2] = { sm, sm + AS_SZ };
    float* Bsb[2] = { sm + 2 * AS_SZ, sm + 2 * AS_SZ + BS_SZ };
    float* Cs = sm;

    const int tid = threadIdx.x, lane = tid & 31, warp = tid >> 5;
    const int wm = warp & 3, wn = warp >> 2;
    const int h0 = blockIdx.x * BN;
    const int t0 = blockIdx.y * BM;

    float acc[2][6][4];
#pragma unroll
    for (int i = 0; i < 2; i++)
#pragma unroll
        for (int j = 0; j < 6; j++)
#pragma unroll
            for (int q = 0; q < 4; q++) acc[i][j][q] = 0.f;

    constexpr int KPE = D_ / BK;        // 90 per expert
    constexpr int KT  = E_ * KPE;       // 720 total

    load_A(Asb[0], g_hidden + (long long)t0 * D_, D_, tid);
    load_B(Bsb[0], w2 + h0, H_, tid);
    cp_commit();

    for (int kt = 0; kt < KT; kt++) {
        const int nkt = kt + 1;
        if (nkt < KT) {
            const int e = nkt / KPE, kk = nkt - e * KPE;
            load_A(Asb[nkt & 1],
                   g_hidden + ((long long)e * T_ + t0) * D_ + kk * BK, D_, tid);
            load_B(Bsb[nkt & 1],
                   w2 + ((long long)e * D_ + kk * BK) * H_ + h0, H_, tid);
            cp_commit();
            cp_wait1();
        } else {
            cp_wait0();
        }
        __syncthreads();
        compute_stage(Asb[kt & 1], Bsb[kt & 1], acc, wm, wn, lane);
        __syncthreads();
    }

    store_acc(Cs, acc, wm, wn, lane);
    __syncthreads();

    for (int idx = tid; idx < BM * BN; idx += 256) {
        const int r = idx / BN, c = idx % BN;
        const int t = t0 + r, h = h0 + c;
        const float* rw = routing + t * E_;
        float bias = 0.f;
#pragma unroll
        for (int e = 0; e < E_; e++) bias += rw[e] * b2[e * H_ + h];
        out[(long long)t * H_ + h] = Cs[r * LDC + c] + bias;
    }
}

// ================= launch ====================
extern "C" void kernel_launch(void* const* d_in, const int* in_sizes, int n_in,
                              void* d_out, int out_size) {
    // Identify inputs by element count (all six are distinct)
    const float *x = nullptr, *rw = nullptr, *w1 = nullptr, *b1 = nullptr,
                *w2 = nullptr, *b2 = nullptr;
    for (int i = 0; i < n_in; i++) {
        const long long s = in_sizes[i];
        const float* p = (const float*)d_in[i];
        if      (s == (long long)T_ * H_)        x  = p;
        else if (s == (long long)T_ * E_)        rw = p;
        else if (s == (long long)E_ * H_ * N2_)  w1 = p;
        else if (s == (long long)E_ * N2_)       b1 = p;
        else if (s == (long long)E_ * D_ * H_)   w2 = p;
        else if (s == (long long)E_ * H_)        b2 = p;
    }
    float* out = (float*)d_out;

    cudaFuncSetAttribute(k_gateup, cudaFuncAttributeMaxDynamicSharedMemorySize, SMEM_BYTES);
    cudaFuncSetAttribute(k_down,   cudaFuncAttributeMaxDynamicSharedMemorySize, SMEM_BYTES);

    dim3 g1(N2_ / BN, T_ / BM, E_);   // 60 x 16 x 8
    k_gateup<<<g1, 256, SMEM_BYTES>>>(x, w1, b1, rw);

    dim3 g2(H_ / BN, T_ / BM);        // 30 x 16
    k_down<<<g2, 256, SMEM_BYTES>>>(w2, b2, rw, out);
}

// round 4
// speedup vs baseline: 1.2484x; 1.2484x over previous
#include <cuda_runtime.h>
#include <cstdint>

#define E_  8
#define T_  2048
#define H_  2880
#define D_  2880
#define N2_ 5760

// pre-rounded (tf32-RNA) copies + intermediate
__device__ float g_xr[(size_t)T_ * H_];
__device__ float g_w1r[(size_t)E_ * H_ * N2_];
__device__ float g_w2r[(size_t)E_ * D_ * H_];
__device__ float g_hidden[(size_t)E_ * T_ * D_];

// ---------------- helpers ----------------
__device__ __forceinline__ unsigned smem_u32(const void* p) {
    return (unsigned)__cvta_generic_to_shared(p);
}
__device__ __forceinline__ void cp16(float* s, const float* g) {
    asm volatile("cp.async.cg.shared.global [%0], [%1], 16;" :: "r"(smem_u32(s)), "l"(g));
}
__device__ __forceinline__ void cp_commit() { asm volatile("cp.async.commit_group;"); }
__device__ __forceinline__ void cp_wait1()  { asm volatile("cp.async.wait_group 1;"); }
__device__ __forceinline__ void cp_wait0()  { asm volatile("cp.async.wait_group 0;"); }

__device__ __forceinline__ float tf32r(float x) {
    uint32_t r; asm("cvt.rna.tf32.f32 %0, %1;" : "=r"(r) : "f"(x));
    return __uint_as_float(r);
}
__device__ __forceinline__ void mma8(float* c, const uint32_t* a, const uint32_t* b) {
    asm volatile("mma.sync.aligned.m16n8k8.row.col.f32.tf32.tf32.f32 "
        "{%0,%1,%2,%3}, {%4,%5,%6,%7}, {%8,%9}, {%0,%1,%2,%3};"
        : "+f"(c[0]), "+f"(c[1]), "+f"(c[2]), "+f"(c[3])
        : "r"(a[0]), "r"(a[1]), "r"(a[2]), "r"(a[3]), "r"(b[0]), "r"(b[1]));
}

// ---------------- tiling ----------------
constexpr int BK  = 32;
constexpr int LDA = 36;                       // A smem row stride (floats)
constexpr int ASF = 128 * LDA;                // A stage floats

template<int BN> struct Cfg {
    static constexpr int LDB = BN + 4;
    static constexpr int NF  = BN / 16;       // frags per warp along N (warp N = BN/2)
    static constexpr int WN  = BN / 2;
    static constexpr int BSF = BK * LDB;      // B stage floats
    static constexpr int STG = ASF + BSF;     // stage floats
    static constexpr int SMEM = 3 * STG * 4;  // bytes
};

// ---------------- stage loads ----------------
__device__ __forceinline__ void load_A(float* As, const float* Ag, int lda, int tid) {
#pragma unroll
    for (int i = 0; i < 4; i++) {
        int c = tid + i * 256;
        int r = c >> 3, q = (c & 7) << 2;     // 128 rows x 8 16B-chunks
        cp16(As + r * LDA + q, Ag + (size_t)r * lda + q);
    }
}
template<int BN>
__device__ __forceinline__ void load_B(float* Bs, const float* Bg, int ldb, int tid) {
    constexpr int CPR = BN / 4;               // chunks per row
    constexpr int CH  = 8 * BN / 256;         // chunks per thread
#pragma unroll
    for (int i = 0; i < CH; i++) {
        int c = tid + i * 256;
        int r = c / CPR, q = (c % CPR) << 2;
        cp16(Bs + r * Cfg<BN>::LDB + q, Bg + (size_t)r * ldb + q);
    }
}

// ---------------- compute stage (no cvt: inputs pre-rounded) ----------------
template<int BN>
__device__ __forceinline__ void compute_stage(const float* __restrict__ As,
                                              const float* __restrict__ Bs,
                                              float (&acc)[2][Cfg<BN>::NF][4],
                                              int wm, int wn, int lane) {
    constexpr int NF = Cfg<BN>::NF, LDB = Cfg<BN>::LDB, WN = Cfg<BN>::WN;
    const int ra = lane >> 2, ca = lane & 3;
#pragma unroll
    for (int ks = 0; ks < 4; ks++) {
        const int k0 = ks * 8;
        uint32_t a[2][4], b[NF][2];
#pragma unroll
        for (int i = 0; i < 2; i++) {
            const float* ap = As + (wm * 32 + i * 16 + ra) * LDA + k0 + ca;
            a[i][0] = __float_as_uint(ap[0]);
            a[i][1] = __float_as_uint(ap[8 * LDA]);
            a[i][2] = __float_as_uint(ap[4]);
            a[i][3] = __float_as_uint(ap[8 * LDA + 4]);
        }
#pragma unroll
        for (int j = 0; j < NF; j++) {
            const float* bp = Bs + (k0 + ca) * LDB + wn * WN + j * 8 + ra;
            b[j][0] = __float_as_uint(bp[0]);
            b[j][1] = __float_as_uint(bp[4 * LDB]);
        }
#pragma unroll
        for (int i = 0; i < 2; i++)
#pragma unroll
            for (int j = 0; j < NF; j++)
                mma8(acc[i][j], a[i], b[j]);
    }
}

// ================= preprocess: tf32-RNA round (vectorized) =================
__global__ void k_round4(const float4* __restrict__ in, float4* __restrict__ out, size_t n4) {
    size_t i = (size_t)blockIdx.x * blockDim.x + threadIdx.x;
    size_t st = (size_t)gridDim.x * blockDim.x;
    for (; i < n4; i += st) {
        float4 v = in[i];
        v.x = tf32r(v.x); v.y = tf32r(v.y); v.z = tf32r(v.z); v.w = tf32r(v.w);
        out[i] = v;
    }
}

// ================= GEMM1: x @ w1 + b1 -> GLU -> routing scale -> g_hidden ==
__global__ void __launch_bounds__(256, 2)
k_gemm1(const float* __restrict__ b1, const float* __restrict__ routing) {
    constexpr int BN = 128, NF = Cfg<BN>::NF;
    extern __shared__ float sm[];
    const int tid = threadIdx.x, lane = tid & 31, warp = tid >> 5;
    const int wm = warp & 3, wn = warp >> 2;
    const int n0 = blockIdx.x * BN;
    const int t0 = blockIdx.y * 128;
    const int e  = blockIdx.z;

    float* As[3]; float* Bs[3];
#pragma unroll
    for (int s = 0; s < 3; s++) { As[s] = sm + s * Cfg<BN>::STG; Bs[s] = As[s] + ASF; }

    const float* Ag = g_xr + (size_t)t0 * H_;
    const float* Bg = g_w1r + (size_t)e * H_ * N2_ + n0;

    float acc[2][NF][4];
#pragma unroll
    for (int i = 0; i < 2; i++)
#pragma unroll
        for (int j = 0; j < NF; j++)
#pragma unroll
            for (int q = 0; q < 4; q++) acc[i][j][q] = 0.f;

    constexpr int KT = H_ / BK;   // 90
    load_A(As[0], Ag, H_, tid);            load_B<BN>(Bs[0], Bg, N2_, tid);            cp_commit();
    load_A(As[1], Ag + BK, H_, tid);       load_B<BN>(Bs[1], Bg + (size_t)BK * N2_, N2_, tid); cp_commit();

    for (int kt = 0; kt < KT; kt++) {
        if (kt == KT - 1) cp_wait0(); else cp_wait1();
        __syncthreads();
        compute_stage<BN>(As[kt % 3], Bs[kt % 3], acc, wm, wn, lane);
        const int nk = kt + 2;
        if (nk < KT) {
            load_A(As[nk % 3], Ag + nk * BK, H_, tid);
            load_B<BN>(Bs[nk % 3], Bg + (size_t)nk * BK * N2_, N2_, tid);
            cp_commit();
        }
    }

    // epilogue: bias slice to smem, GLU from registers
    __syncthreads();
    if (tid < BN) sm[tid] = b1[(size_t)e * N2_ + n0 + tid];
    __syncthreads();

    const int ra = lane >> 2, ca2 = 2 * (lane & 3);
    float rw[2][2];
#pragma unroll
    for (int i = 0; i < 2; i++)
#pragma unroll
        for (int h = 0; h < 2; h++)
            rw[i][h] = routing[(size_t)(t0 + wm * 32 + i * 16 + h * 8 + ra) * E_ + e];

#pragma unroll
    for (int i = 0; i < 2; i++)
#pragma unroll
        for (int h = 0; h < 2; h++) {
            const int row = wm * 32 + i * 16 + h * 8 + ra;
            float* gh = g_hidden + ((size_t)e * T_ + t0 + row) * D_ + (n0 >> 1);
#pragma unroll
            for (int j = 0; j < NF; j++) {
                const int C = wn * Cfg<BN>::WN + j * 8 + ca2;
                float gate = acc[i][j][2 * h]     + sm[C];
                float up   = acc[i][j][2 * h + 1] + sm[C + 1];
                gate = fminf(gate, 7.0f);
                up   = fminf(fmaxf(up, -7.0f), 7.0f);
                const float glu = gate / (1.0f + __expf(-1.702f * gate));
                gh[C >> 1] = tf32r((up + 1.0f) * glu * rw[i][h]);
            }
        }
}

// ================= GEMM2: hidden @ w2 (flat K over e,d) + routed bias ======
__global__ void __launch_bounds__(256, 2)
k_gemm2(const float* __restrict__ b2, const float* __restrict__ routing,
        float* __restrict__ out) {
    constexpr int BN = 96, NF = Cfg<BN>::NF;
    extern __shared__ float sm[];
    const int tid = threadIdx.x, lane = tid & 31, warp = tid >> 5;
    const int wm = warp & 3, wn = warp >> 2;
    const int h0 = blockIdx.x * BN;
    const int t0 = blockIdx.y * 128;

    float* As[3]; float* Bs[3];
#pragma unroll
    for (int s = 0; s < 3; s++) { As[s] = sm + s * Cfg<BN>::STG; Bs[s] = As[s] + ASF; }

    float acc[2][NF][4];
#pragma unroll
    for (int i = 0; i < 2; i++)
#pragma unroll
        for (int j = 0; j < NF; j++)
#pragma unroll
            for (int q = 0; q < 4; q++) acc[i][j][q] = 0.f;

    constexpr int KPE = D_ / BK;            // 90
    constexpr int KT  = E_ * KPE;           // 720

    auto Ag_at = [&](int kt) {
        const int e = kt / KPE, kk = kt - e * KPE;
        return g_hidden + ((size_t)e * T_ + t0) * D_ + kk * BK;
    };
    auto Bg_at = [&](int kt) {
        const int e = kt / KPE, kk = kt - e * KPE;
        return g_w2r + ((size_t)e * D_ + kk * BK) * H_ + h0;
    };

    load_A(As[0], Ag_at(0), D_, tid); load_B<BN>(Bs[0], Bg_at(0), H_, tid); cp_commit();
    load_A(As[1], Ag_at(1), D_, tid); load_B<BN>(Bs[1], Bg_at(1), H_, tid); cp_commit();

    for (int kt = 0; kt < KT; kt++) {
        if (kt == KT - 1) cp_wait0(); else cp_wait1();
        __syncthreads();
        compute_stage<BN>(As[kt % 3], Bs[kt % 3], acc, wm, wn, lane);
        const int nk = kt + 2;
        if (nk < KT) {
            load_A(As[nk % 3], Ag_at(nk), D_, tid);
            load_B<BN>(Bs[nk % 3], Bg_at(nk), H_, tid);
            cp_commit();
        }
    }

    // epilogue: routed down-bias, direct from registers
    __syncthreads();
    for (int i = tid; i < E_ * BN; i += 256) {
        const int ee = i / BN, c = i - ee * BN;
        sm[i] = b2[(size_t)ee * H_ + h0 + c];
    }
    __syncthreads();

    const int ra = lane >> 2, ca2 = 2 * (lane & 3);
#pragma unroll
    for (int i = 0; i < 2; i++)
#pragma unroll
        for (int h = 0; h < 2; h++) {
            const int t = t0 + wm * 32 + i * 16 + h * 8 + ra;
            const float4 r03 = ((const float4*)routing)[(size_t)t * 2];
            const float4 r47 = ((const float4*)routing)[(size_t)t * 2 + 1];
            const float rwv[8] = { r03.x, r03.y, r03.z, r03.w, r47.x, r47.y, r47.z, r47.w };
            float* orow = out + (size_t)t * H_ + h0;
#pragma unroll
            for (int j = 0; j < NF; j++) {
                const int C = wn * Cfg<BN>::WN + j * 8 + ca2;
                float v0 = acc[i][j][2 * h];
                float v1 = acc[i][j][2 * h + 1];
#pragma unroll
                for (int ee = 0; ee < E_; ee++) {
                    v0 += rwv[ee] * sm[ee * BN + C];
                    v1 += rwv[ee] * sm[ee * BN + C + 1];
                }
                *(float2*)(orow + C) = make_float2(v0, v1);
            }
        }
}

// ================= host ====================
extern "C" void kernel_launch(void* const* d_in, const int* in_sizes, int n_in,
                              void* d_out, int out_size) {
    const float *x = nullptr, *rw = nullptr, *w1 = nullptr, *b1 = nullptr,
                *w2 = nullptr, *b2 = nullptr;
    for (int i = 0; i < n_in; i++) {
        const long long s = in_sizes[i];
        const float* p = (const float*)d_in[i];
        if      (s == (long long)T_ * H_)        x  = p;
        else if (s == (long long)T_ * E_)        rw = p;
        else if (s == (long long)E_ * H_ * N2_)  w1 = p;
        else if (s == (long long)E_ * N2_)       b1 = p;
        else if (s == (long long)E_ * D_ * H_)   w2 = p;
        else if (s == (long long)E_ * H_)        b2 = p;
    }
    float* out = (float*)d_out;

    void *p_xr, *p_w1r, *p_w2r;
    cudaGetSymbolAddress(&p_xr,  g_xr);
    cudaGetSymbolAddress(&p_w1r, g_w1r);
    cudaGetSymbolAddress(&p_w2r, g_w2r);

    cudaFuncSetAttribute(k_gemm1, cudaFuncAttributeMaxDynamicSharedMemorySize, Cfg<128>::SMEM);
    cudaFuncSetAttribute(k_gemm2, cudaFuncAttributeMaxDynamicSharedMemorySize, Cfg<96>::SMEM);

    // preprocess: round to tf32-RNA once
    k_round4<<<4096, 256>>>((const float4*)x,  (float4*)p_xr,  (size_t)T_ * H_ / 4);
    k_round4<<<8192, 256>>>((const float4*)w1, (float4*)p_w1r, (size_t)E_ * H_ * N2_ / 4);
    k_round4<<<8192, 256>>>((const float4*)w2, (float4*)p_w2r, (size_t)E_ * D_ * H_ / 4);

    k_gemm1<<<dim3(N2_ / 128, T_ / 128, E_), 256, Cfg<128>::SMEM>>>(b1, rw);
    k_gemm2<<<dim3(H_ / 96, T_ / 128), 256, Cfg<96>::SMEM>>>(b2, rw, out);
}

// round 5
// speedup vs baseline: 1.8296x; 1.4656x over previous
#include <cuda_runtime.h>
#include <cstdint>

#define E_  8
#define T_  2048
#define H_  2880
#define D_  2880
#define N2_ 5760

// tf32-rounded copies; weights transposed to K-major
__device__ float g_xr[(size_t)T_ * H_];                  // [T][H]
__device__ float g_w1t[(size_t)E_ * N2_ * H_];           // [E][N2][H]
__device__ float g_w2t[(size_t)E_ * H_ * D_];            // [E][H][D]
__device__ float g_hidden[(size_t)E_ * T_ * D_];         // [E][T][D]

// ---------------- helpers ----------------
__device__ __forceinline__ unsigned smem_u32(const void* p) {
    return (unsigned)__cvta_generic_to_shared(p);
}
__device__ __forceinline__ void cp16(float* s, const float* g) {
    asm volatile("cp.async.cg.shared.global [%0], [%1], 16;" :: "r"(smem_u32(s)), "l"(g));
}
__device__ __forceinline__ void cp_commit() { asm volatile("cp.async.commit_group;"); }
__device__ __forceinline__ void cp_wait1()  { asm volatile("cp.async.wait_group 1;"); }
__device__ __forceinline__ void cp_wait0()  { asm volatile("cp.async.wait_group 0;"); }

__device__ __forceinline__ float tf32r(float x) {
    uint32_t r; asm("cvt.rna.tf32.f32 %0, %1;" : "=r"(r) : "f"(x));
    return __uint_as_float(r);
}
__device__ __forceinline__ void mma8(float* c, const uint32_t* a, const uint32_t* b) {
    asm volatile("mma.sync.aligned.m16n8k8.row.col.f32.tf32.tf32.f32 "
        "{%0,%1,%2,%3}, {%4,%5,%6,%7}, {%8,%9}, {%0,%1,%2,%3};"
        : "+f"(c[0]), "+f"(c[1]), "+f"(c[2]), "+f"(c[3])
        : "r"(a[0]), "r"(a[1]), "r"(a[2]), "r"(a[3]), "r"(b[0]), "r"(b[1]));
}
__device__ __forceinline__ void ldsm4(uint32_t& r0, uint32_t& r1, uint32_t& r2, uint32_t& r3,
                                      uint32_t addr) {
    asm volatile("ldmatrix.sync.aligned.m8n8.x4.shared.b16 {%0,%1,%2,%3}, [%4];"
        : "=r"(r0), "=r"(r1), "=r"(r2), "=r"(r3) : "r"(addr));
}

// ---------------- tiling ----------------
constexpr int BK = 32;                                // K per stage; rows are 128B
constexpr int A_ROWS = 128;
constexpr int A_FL = A_ROWS * 32;                     // A stage floats
template<int BN> struct Cfg {
    static constexpr int NF   = BN / 16;              // N frags per warp (warp N = BN/2)
    static constexpr int WN   = BN / 2;
    static constexpr int STGF = (A_ROWS + BN) * 32;   // stage floats
    static constexpr int SMEM = 3 * STGF * 4;         // bytes
};

// swizzled tile load: ROWS x 32 floats, 16B chunks, chunk' = chunk ^ (row&7)
template<int ROWS>
__device__ __forceinline__ void load_tile(float* S, const float* G, int lda, int tid) {
#pragma unroll
    for (int i = 0; i < ROWS * 8 / 256; i++) {
        int c = tid + i * 256;
        int r = c >> 3, q = c & 7;
        int qs = q ^ (r & 7);
        cp16(S + r * 32 + qs * 4, G + (size_t)r * lda + q * 4);
    }
}

// ---------------- compute stage: ldmatrix fragment feed ----------------
template<int BN>
__device__ __forceinline__ void compute_stage(uint32_t sA, uint32_t sB,
                                              const uint32_t (&aOff)[2],
                                              const uint32_t (&bOff)[Cfg<BN>::NF / 2],
                                              float (&acc)[2][Cfg<BN>::NF][4]) {
    constexpr int NF = Cfg<BN>::NF;
#pragma unroll
    for (int ks = 0; ks < 4; ks++) {
        const uint32_t kx = ks * 32;                  // byte XOR for k-chunk
        uint32_t a[2][4], b[NF][2];
#pragma unroll
        for (int i = 0; i < 2; i++)
            ldsm4(a[i][0], a[i][1], a[i][2], a[i][3], sA + (aOff[i] ^ kx));
#pragma unroll
        for (int jp = 0; jp < NF / 2; jp++) {
            uint32_t r0, r1, r2, r3;
            ldsm4(r0, r1, r2, r3, sB + (bOff[jp] ^ kx));
            b[2 * jp][0] = r0; b[2 * jp][1] = r1;
            b[2 * jp + 1][0] = r2; b[2 * jp + 1][1] = r3;
        }
#pragma unroll
        for (int i = 0; i < 2; i++)
#pragma unroll
            for (int j = 0; j < NF; j++)
                mma8(acc[i][j], a[i], b[j]);
    }
}

// per-lane ldmatrix base offsets (bytes into stage region)
__device__ __forceinline__ void frag_offsets_A(uint32_t (&aOff)[2], int wm, int lane) {
    const int rr = lane & 7, mm = lane >> 3;
#pragma unroll
    for (int i = 0; i < 2; i++) {
        const int row = wm * 32 + i * 16 + (mm & 1) * 8 + rr;   // A: bit0 = +8 rows
        aOff[i] = row * 128 + ((((mm >> 1) ^ (row & 7)) & 7) << 4);  // bit1 = +4 cols
    }
}
template<int BN>
__device__ __forceinline__ void frag_offsets_B(uint32_t (&bOff)[Cfg<BN>::NF / 2], int wn, int lane) {
    const int rr = lane & 7, mm = lane >> 3;
#pragma unroll
    for (int jp = 0; jp < Cfg<BN>::NF / 2; jp++) {
        const int row = wn * Cfg<BN>::WN + (jp * 2 + (mm >> 1)) * 8 + rr;  // bit1 = +8 n-rows
        bOff[jp] = row * 128 + ((((mm & 1) ^ (row & 7)) & 7) << 4);        // bit0 = +4 cols
    }
}

// ================= preprocess =================
__global__ void k_round4(const float4* __restrict__ in, float4* __restrict__ out, size_t n4) {
    size_t i = (size_t)blockIdx.x * blockDim.x + threadIdx.x;
    size_t st = (size_t)gridDim.x * blockDim.x;
    for (; i < n4; i += st) {
        float4 v = in[i];
        v.x = tf32r(v.x); v.y = tf32r(v.y); v.z = tf32r(v.z); v.w = tf32r(v.w);
        out[i] = v;
    }
}
// [z][R][C] -> [z][C][R], tf32-rounded
__global__ void k_transpose(const float* __restrict__ in, float* __restrict__ out, int R, int C) {
    __shared__ float t[32][33];
    const float* iz = in + (size_t)blockIdx.z * R * C;
    float* oz = out + (size_t)blockIdx.z * R * C;
    int c0 = blockIdx.x * 32, r0 = blockIdx.y * 32;
#pragma unroll
    for (int i = 0; i < 32; i += 8)
        t[threadIdx.y + i][threadIdx.x] = iz[(size_t)(r0 + threadIdx.y + i) * C + c0 + threadIdx.x];
    __syncthreads();
#pragma unroll
    for (int i = 0; i < 32; i += 8)
        oz[(size_t)(c0 + threadIdx.y + i) * R + r0 + threadIdx.x] = tf32r(t[threadIdx.x][threadIdx.y + i]);
}

// ================= GEMM1: x @ w1t^T + b1 -> GLU -> routing -> g_hidden ======
__global__ void __launch_bounds__(256, 2)
k_gemm1(const float* __restrict__ b1, const float* __restrict__ routing) {
    constexpr int BN = 128, NF = Cfg<BN>::NF;
    extern __shared__ __align__(128) float sm[];
    const int tid = threadIdx.x, lane = tid & 31, warp = tid >> 5;
    const int wm = warp & 3, wn = warp >> 2;
    const int n0 = blockIdx.x * BN;
    const int t0 = blockIdx.y * 128;
    const int e  = blockIdx.z;

    const uint32_t sb = smem_u32(sm);
    float* Af[3]; float* Bf[3];
#pragma unroll
    for (int s = 0; s < 3; s++) { Af[s] = sm + s * Cfg<BN>::STGF; Bf[s] = Af[s] + A_FL; }

    const float* Ag = g_xr + (size_t)t0 * H_;
    const float* Bg = g_w1t + ((size_t)e * N2_ + n0) * H_;

    uint32_t aOff[2], bOff[NF / 2];
    frag_offsets_A(aOff, wm, lane);
    frag_offsets_B<BN>(bOff, wn, lane);

    float acc[2][NF][4];
#pragma unroll
    for (int i = 0; i < 2; i++)
#pragma unroll
        for (int j = 0; j < NF; j++)
#pragma unroll
            for (int q = 0; q < 4; q++) acc[i][j][q] = 0.f;

    constexpr int KT = H_ / BK;  // 90
    load_tile<128>(Af[0], Ag, H_, tid);      load_tile<BN>(Bf[0], Bg, H_, tid);      cp_commit();
    load_tile<128>(Af[1], Ag + BK, H_, tid); load_tile<BN>(Bf[1], Bg + BK, H_, tid); cp_commit();

    for (int kt = 0; kt < KT; kt++) {
        if (kt == KT - 1) cp_wait0(); else cp_wait1();
        __syncthreads();
        const int s = kt % 3;
        compute_stage<BN>(sb + s * Cfg<BN>::STGF * 4, sb + (s * Cfg<BN>::STGF + A_FL) * 4,
                          aOff, bOff, acc);
        const int nk = kt + 2;
        if (nk < KT) {
            load_tile<128>(Af[nk % 3], Ag + nk * BK, H_, tid);
            load_tile<BN>(Bf[nk % 3], Bg + nk * BK, H_, tid);
            cp_commit();
        }
    }

    // epilogue
    __syncthreads();
    if (tid < BN) sm[tid] = b1[(size_t)e * N2_ + n0 + tid];
    __syncthreads();

    const int ra = lane >> 2, ca2 = 2 * (lane & 3);
#pragma unroll
    for (int i = 0; i < 2; i++)
#pragma unroll
        for (int h = 0; h < 2; h++) {
            const int row = wm * 32 + i * 16 + h * 8 + ra;
            const float rw = routing[(size_t)(t0 + row) * E_ + e];
            float* gh = g_hidden + ((size_t)e * T_ + t0 + row) * D_ + (n0 >> 1);
#pragma unroll
            for (int j = 0; j < NF; j++) {
                const int C = wn * Cfg<BN>::WN + j * 8 + ca2;
                float gate = acc[i][j][2 * h]     + sm[C];
                float up   = acc[i][j][2 * h + 1] + sm[C + 1];
                gate = fminf(gate, 7.0f);
                up   = fminf(fmaxf(up, -7.0f), 7.0f);
                const float glu = gate / (1.0f + __expf(-1.702f * gate));
                gh[C >> 1] = tf32r((up + 1.0f) * glu * rw);
            }
        }
}

// ================= GEMM2: hidden @ w2t^T (flat K) + routed bias =============
__global__ void __launch_bounds__(256, 2)
k_gemm2(const float* __restrict__ b2, const float* __restrict__ routing,
        float* __restrict__ out) {
    constexpr int BN = 96, NF = Cfg<BN>::NF;
    extern __shared__ __align__(128) float sm[];
    const int tid = threadIdx.x, lane = tid & 31, warp = tid >> 5;
    const int wm = warp & 3, wn = warp >> 2;
    const int h0 = blockIdx.x * BN;
    const int t0 = blockIdx.y * 128;

    const uint32_t sb = smem_u32(sm);
    float* Af[3]; float* Bf[3];
#pragma unroll
    for (int s = 0; s < 3; s++) { Af[s] = sm + s * Cfg<BN>::STGF; Bf[s] = Af[s] + A_FL; }

    uint32_t aOff[2], bOff[NF / 2];
    frag_offsets_A(aOff, wm, lane);
    frag_offsets_B<BN>(bOff, wn, lane);

    float acc[2][NF][4];
#pragma unroll
    for (int i = 0; i < 2; i++)
#pragma unroll
        for (int j = 0; j < NF; j++)
#pragma unroll
            for (int q = 0; q < 4; q++) acc[i][j][q] = 0.f;

    constexpr int KPE = D_ / BK;       // 90
    constexpr int KT  = E_ * KPE;      // 720

    load_tile<128>(Af[0], g_hidden + (size_t)t0 * D_, D_, tid);
    load_tile<BN>(Bf[0], g_w2t + (size_t)h0 * D_, D_, tid);
    cp_commit();
    load_tile<128>(Af[1], g_hidden + (size_t)t0 * D_ + BK, D_, tid);
    load_tile<BN>(Bf[1], g_w2t + (size_t)h0 * D_ + BK, D_, tid);
    cp_commit();

    int ez = 0, kk = 2;                // next (e, k-chunk) to load
    for (int kt = 0; kt < KT; kt++) {
        if (kt == KT - 1) cp_wait0(); else cp_wait1();
        __syncthreads();
        const int s = kt % 3;
        compute_stage<BN>(sb + s * Cfg<BN>::STGF * 4, sb + (s * Cfg<BN>::STGF + A_FL) * 4,
                          aOff, bOff, acc);
        const int nk = kt + 2;
        if (nk < KT) {
            load_tile<128>(Af[nk % 3], g_hidden + ((size_t)ez * T_ + t0) * D_ + kk * BK, D_, tid);
            load_tile<BN>(Bf[nk % 3], g_w2t + ((size_t)ez * H_ + h0) * D_ + kk * BK, D_, tid);
            cp_commit();
            if (++kk == KPE) { kk = 0; ez++; }
        }
    }

    // epilogue: routed down-bias
    __syncthreads();
    for (int i = tid; i < E_ * BN; i += 256) {
        const int ee = i / BN, c = i - ee * BN;
        sm[i] = b2[(size_t)ee * H_ + h0 + c];
    }
    __syncthreads();

    const int ra = lane >> 2, ca2 = 2 * (lane & 3);
#pragma unroll
    for (int i = 0; i < 2; i++)
#pragma unroll
        for (int h = 0; h < 2; h++) {
            const int t = t0 + wm * 32 + i * 16 + h * 8 + ra;
            const float4 r03 = ((const float4*)routing)[(size_t)t * 2];
            const float4 r47 = ((const float4*)routing)[(size_t)t * 2 + 1];
            const float rwv[8] = { r03.x, r03.y, r03.z, r03.w, r47.x, r47.y, r47.z, r47.w };
            float* orow = out + (size_t)t * H_ + h0;
#pragma unroll
            for (int j = 0; j < NF; j++) {
                const int C = wn * Cfg<BN>::WN + j * 8 + ca2;
                float v0 = acc[i][j][2 * h];
                float v1 = acc[i][j][2 * h + 1];
#pragma unroll
                for (int ee = 0; ee < E_; ee++) {
                    v0 += rwv[ee] * sm[ee * BN + C];
                    v1 += rwv[ee] * sm[ee * BN + C + 1];
                }
                *(float2*)(orow + C) = make_float2(v0, v1);
            }
        }
}

// ================= host ====================
extern "C" void kernel_launch(void* const* d_in, const int* in_sizes, int n_in,
                              void* d_out, int out_size) {
    const float *x = nullptr, *rw = nullptr, *w1 = nullptr, *b1 = nullptr,
                *w2 = nullptr, *b2 = nullptr;
    for (int i = 0; i < n_in; i++) {
        const long long s = in_sizes[i];
        const float* p = (const float*)d_in[i];
        if      (s == (long long)T_ * H_)        x  = p;
        else if (s == (long long)T_ * E_)        rw = p;
        else if (s == (long long)E_ * H_ * N2_)  w1 = p;
        else if (s == (long long)E_ * N2_)       b1 = p;
        else if (s == (long long)E_ * D_ * H_)   w2 = p;
        else if (s == (long long)E_ * H_)        b2 = p;
    }
    float* out = (float*)d_out;

    void *p_xr, *p_w1t, *p_w2t;
    cudaGetSymbolAddress(&p_xr,  g_xr);
    cudaGetSymbolAddress(&p_w1t, g_w1t);
    cudaGetSymbolAddress(&p_w2t, g_w2t);

    cudaFuncSetAttribute(k_gemm1, cudaFuncAttributeMaxDynamicSharedMemorySize, Cfg<128>::SMEM);
    cudaFuncSetAttribute(k_gemm2, cudaFuncAttributeMaxDynamicSharedMemorySize, Cfg<96>::SMEM);

    // preprocess: round x; transpose+round weights to K-major
    k_round4<<<4096, 256>>>((const float4*)x, (float4*)p_xr, (size_t)T_ * H_ / 4);
    dim3 tb(32, 8);
    k_transpose<<<dim3(N2_ / 32, H_ / 32, E_), tb>>>(w1, (float*)p_w1t, H_, N2_);
    k_transpose<<<dim3(H_ / 32, D_ / 32, E_), tb>>>(w2, (float*)p_w2t, D_, H_);

    k_gemm1<<<dim3(N2_ / 128, T_ / 128, E_), 256, Cfg<128>::SMEM>>>(b1, rw);
    k_gemm2<<<dim3(H_ / 96, T_ / 128), 256, Cfg<96>::SMEM>>>(b2, rw, out);
}

// round 6
// speedup vs baseline: 1.8901x; 1.0331x over previous
#include <cuda_runtime.h>
#include <cstdint>

#define E_  8
#define T_  2048
#define H_  2880
#define D_  2880
#define N2_ 5760

__device__ float g_xr[(size_t)T_ * H_];
__device__ float g_w1t[(size_t)E_ * N2_ * H_];
__device__ float g_w2t[(size_t)E_ * H_ * D_];
__device__ float g_hidden[(size_t)E_ * T_ * D_];

// ---------------- helpers ----------------
__device__ __forceinline__ unsigned smem_u32(const void* p) {
    return (unsigned)__cvta_generic_to_shared(p);
}
__device__ __forceinline__ void cp16(float* s, const float* g) {
    asm volatile("cp.async.cg.shared.global [%0], [%1], 16;" :: "r"(smem_u32(s)), "l"(g));
}
__device__ __forceinline__ void cp_commit() { asm volatile("cp.async.commit_group;"); }
__device__ __forceinline__ void cp_wait2()  { asm volatile("cp.async.wait_group 2;"); }
__device__ __forceinline__ void cp_wait1()  { asm volatile("cp.async.wait_group 1;"); }
__device__ __forceinline__ void cp_wait0()  { asm volatile("cp.async.wait_group 0;"); }

__device__ __forceinline__ float tf32r(float x) {
    uint32_t r; asm("cvt.rna.tf32.f32 %0, %1;" : "=r"(r) : "f"(x));
    return __uint_as_float(r);
}
__device__ __forceinline__ void mma8(float* c, const uint32_t* a, const uint32_t* b) {
    asm volatile("mma.sync.aligned.m16n8k8.row.col.f32.tf32.tf32.f32 "
        "{%0,%1,%2,%3}, {%4,%5,%6,%7}, {%8,%9}, {%0,%1,%2,%3};"
        : "+f"(c[0]), "+f"(c[1]), "+f"(c[2]), "+f"(c[3])
        : "r"(a[0]), "r"(a[1]), "r"(a[2]), "r"(a[3]), "r"(b[0]), "r"(b[1]));
}
__device__ __forceinline__ void ldsm4(uint32_t& r0, uint32_t& r1, uint32_t& r2, uint32_t& r3,
                                      uint32_t addr) {
    asm volatile("ldmatrix.sync.aligned.m8n8.x4.shared.b16 {%0,%1,%2,%3}, [%4];"
        : "=r"(r0), "=r"(r1), "=r"(r2), "=r"(r3) : "r"(addr));
}
__device__ __forceinline__ void ldsm2(uint32_t& r0, uint32_t& r1, uint32_t addr) {
    asm volatile("ldmatrix.sync.aligned.m8n8.x2.shared.b16 {%0,%1}, [%2];"
        : "=r"(r0), "=r"(r1) : "r"(addr));
}

// ---------------- tiling ----------------
constexpr int BM = 256, BN = 160, BK = 32;
constexpr int NT = 512;                     // threads
constexpr int WN = 40, NF = 5;              // per-warp N, N frags
constexpr int A_FL = BM * 32;               // 8192 floats
constexpr int B_FL = BN * 32;               // 5120 floats
constexpr int STGF = A_FL + B_FL;           // 13312 floats (52 KB)
constexpr int STAGES = 4;
constexpr int SMEM_B = STAGES * STGF * 4;   // 212992 B

// swizzled loads (rows x 32 floats; chunk' = chunk ^ (row&7))
__device__ __forceinline__ void load_A(float* S, const float* G, int lda, int tid) {
#pragma unroll
    for (int i = 0; i < 4; i++) {                    // 2048 chunks / 512
        int c = tid + i * NT;
        int r = c >> 3, q = c & 7;
        cp16(S + r * 32 + (q ^ (r & 7)) * 4, G + (size_t)r * lda + q * 4);
    }
}
__device__ __forceinline__ void load_B(float* S, const float* G, int lda, int tid) {
#pragma unroll
    for (int i = 0; i < 3; i++) {                    // 1280 chunks
        int c = tid + i * NT;
        if (c < BN * 8) {
            int r = c >> 3, q = c & 7;
            cp16(S + r * 32 + (q ^ (r & 7)) * 4, G + (size_t)r * lda + q * 4);
        }
    }
}

// per-lane ldmatrix base offsets
__device__ __forceinline__ void frag_offsets(uint32_t (&aOff)[4], uint32_t (&bOff)[3],
                                             int wm, int wn, int lane) {
    const int rr = lane & 7, mm = lane >> 3;
#pragma unroll
    for (int i = 0; i < 4; i++) {
        const int row = wm * 64 + i * 16 + (mm & 1) * 8 + rr;
        aOff[i] = row * 128 + ((((mm >> 1) ^ (row & 7)) & 7) << 4);
    }
#pragma unroll
    for (int jp = 0; jp < 2; jp++) {
        const int row = wn * WN + (jp * 2 + (mm >> 1)) * 8 + rr;
        bOff[jp] = row * 128 + ((((mm & 1) ^ (row & 7)) & 7) << 4);
    }
    {   // x2 frag: lanes 0-15 supply addrs; mask mm to keep others in-range
        const int m2 = mm & 1;
        const int row = wn * WN + 32 + rr;
        bOff[2] = row * 128 + (((m2 ^ (row & 7)) & 7) << 4);
    }
}

__device__ __forceinline__ void compute_stage(uint32_t sA, uint32_t sB,
                                              const uint32_t (&aOff)[4],
                                              const uint32_t (&bOff)[3],
                                              float (&acc)[4][NF][4]) {
#pragma unroll
    for (int ks = 0; ks < 4; ks++) {
        const uint32_t kx = ks * 32;
        uint32_t a[4][4], b[NF][2];
#pragma unroll
        for (int i = 0; i < 4; i++)
            ldsm4(a[i][0], a[i][1], a[i][2], a[i][3], sA + (aOff[i] ^ kx));
        ldsm4(b[0][0], b[0][1], b[1][0], b[1][1], sB + (bOff[0] ^ kx));
        ldsm4(b[2][0], b[2][1], b[3][0], b[3][1], sB + (bOff[1] ^ kx));
        ldsm2(b[4][0], b[4][1], sB + (bOff[2] ^ kx));
#pragma unroll
        for (int i = 0; i < 4; i++)
#pragma unroll
            for (int j = 0; j < NF; j++)
                mma8(acc[i][j], a[i], b[j]);
    }
}

// ================= preprocess =================
__global__ void k_round4(const float4* __restrict__ in, float4* __restrict__ out, size_t n4) {
    size_t i = (size_t)blockIdx.x * blockDim.x + threadIdx.x;
    size_t st = (size_t)gridDim.x * blockDim.x;
    for (; i < n4; i += st) {
        float4 v = in[i];
        v.x = tf32r(v.x); v.y = tf32r(v.y); v.z = tf32r(v.z); v.w = tf32r(v.w);
        out[i] = v;
    }
}
__global__ void k_transpose(const float* __restrict__ in, float* __restrict__ out, int R, int C) {
    __shared__ float t[32][33];
    const float* iz = in + (size_t)blockIdx.z * R * C;
    float* oz = out + (size_t)blockIdx.z * R * C;
    int c0 = blockIdx.x * 32, r0 = blockIdx.y * 32;
#pragma unroll
    for (int i = 0; i < 32; i += 8)
        t[threadIdx.y + i][threadIdx.x] = iz[(size_t)(r0 + threadIdx.y + i) * C + c0 + threadIdx.x];
    __syncthreads();
#pragma unroll
    for (int i = 0; i < 32; i += 8)
        oz[(size_t)(c0 + threadIdx.y + i) * R + r0 + threadIdx.x] = tf32r(t[threadIdx.x][threadIdx.y + i]);
}

// ================= GEMM1 =================
__global__ void __launch_bounds__(NT, 1)
k_gemm1(const float* __restrict__ b1, const float* __restrict__ routing) {
    extern __shared__ __align__(128) float sm[];
    const int tid = threadIdx.x, lane = tid & 31, warp = tid >> 5;
    const int wm = warp & 3, wn = warp >> 2;
    const int n0 = blockIdx.x * BN;
    const int t0 = blockIdx.y * BM;
    const int e  = blockIdx.z;

    const uint32_t sb = smem_u32(sm);
    const float* Ag = g_xr + (size_t)t0 * H_;
    const float* Bg = g_w1t + ((size_t)e * N2_ + n0) * H_;

    uint32_t aOff[4], bOff[3];
    frag_offsets(aOff, bOff, wm, wn, lane);

    float acc[4][NF][4];
#pragma unroll
    for (int i = 0; i < 4; i++)
#pragma unroll
        for (int j = 0; j < NF; j++)
#pragma unroll
            for (int q = 0; q < 4; q++) acc[i][j][q] = 0.f;

    constexpr int KT = H_ / BK;   // 90
#pragma unroll
    for (int s = 0; s < 3; s++) {
        load_A(sm + s * STGF, Ag + s * BK, H_, tid);
        load_B(sm + s * STGF + A_FL, Bg + s * BK, H_, tid);
        cp_commit();
    }

    for (int kt = 0; kt < KT; kt++) {
        if (kt <= KT - 3) cp_wait2(); else if (kt == KT - 2) cp_wait1(); else cp_wait0();
        __syncthreads();
        const int s = kt & 3;
        compute_stage(sb + s * STGF * 4, sb + (s * STGF + A_FL) * 4, aOff, bOff, acc);
        const int nk = kt + 3;
        if (nk < KT) {
            const int ns = nk & 3;
            load_A(sm + ns * STGF, Ag + nk * BK, H_, tid);
            load_B(sm + ns * STGF + A_FL, Bg + nk * BK, H_, tid);
            cp_commit();
        }
    }

    __syncthreads();
    if (tid < BN) sm[tid] = b1[(size_t)e * N2_ + n0 + tid];
    __syncthreads();

    const int ra = lane >> 2, ca2 = 2 * (lane & 3);
#pragma unroll
    for (int i = 0; i < 4; i++)
#pragma unroll
        for (int h = 0; h < 2; h++) {
            const int row = wm * 64 + i * 16 + h * 8 + ra;
            const float rw = routing[(size_t)(t0 + row) * E_ + e];
            float* gh = g_hidden + ((size_t)e * T_ + t0 + row) * D_ + (n0 >> 1);
#pragma unroll
            for (int j = 0; j < NF; j++) {
                const int C = wn * WN + j * 8 + ca2;
                float gate = acc[i][j][2 * h]     + sm[C];
                float up   = acc[i][j][2 * h + 1] + sm[C + 1];
                gate = fminf(gate, 7.0f);
                up   = fminf(fmaxf(up, -7.0f), 7.0f);
                const float glu = gate / (1.0f + __expf(-1.702f * gate));
                gh[C >> 1] = tf32r((up + 1.0f) * glu * rw);
            }
        }
}

// ================= GEMM2 =================
__global__ void __launch_bounds__(NT, 1)
k_gemm2(const float* __restrict__ b2, const float* __restrict__ routing,
        float* __restrict__ out) {
    extern __shared__ __align__(128) float sm[];
    const int tid = threadIdx.x, lane = tid & 31, warp = tid >> 5;
    const int wm = warp & 3, wn = warp >> 2;
    const int h0 = blockIdx.x * BN;
    const int t0 = blockIdx.y * BM;

    const uint32_t sb = smem_u32(sm);
    uint32_t aOff[4], bOff[3];
    frag_offsets(aOff, bOff, wm, wn, lane);

    float acc[4][NF][4];
#pragma unroll
    for (int i = 0; i < 4; i++)
#pragma unroll
        for (int j = 0; j < NF; j++)
#pragma unroll
            for (int q = 0; q < 4; q++) acc[i][j][q] = 0.f;

    constexpr int KPE = D_ / BK;   // 90
    constexpr int KT  = E_ * KPE;  // 720

#pragma unroll
    for (int s = 0; s < 3; s++) {
        load_A(sm + s * STGF, g_hidden + (size_t)t0 * D_ + s * BK, D_, tid);
        load_B(sm + s * STGF + A_FL, g_w2t + (size_t)h0 * D_ + s * BK, D_, tid);
        cp_commit();
    }

    int ez = 0, kk = 3;            // next (e, k-chunk) to load
    for (int kt = 0; kt < KT; kt++) {
        if (kt <= KT - 3) cp_wait2(); else if (kt == KT - 2) cp_wait1(); else cp_wait0();
        __syncthreads();
        const int s = kt & 3;
        compute_stage(sb + s * STGF * 4, sb + (s * STGF + A_FL) * 4, aOff, bOff, acc);
        const int nk = kt + 3;
        if (nk < KT) {
            const int ns = nk & 3;
            load_A(sm + ns * STGF, g_hidden + ((size_t)ez * T_ + t0) * D_ + kk * BK, D_, tid);
            load_B(sm + ns * STGF + A_FL, g_w2t + ((size_t)ez * H_ + h0) * D_ + kk * BK, D_, tid);
            cp_commit();
            if (++kk == KPE) { kk = 0; ez++; }
        }
    }

    __syncthreads();
    for (int i = tid; i < E_ * BN; i += NT) {
        const int ee = i / BN, c = i - ee * BN;
        sm[i] = b2[(size_t)ee * H_ + h0 + c];
    }
    __syncthreads();

    const int ra = lane >> 2, ca2 = 2 * (lane & 3);
#pragma unroll
    for (int i = 0; i < 4; i++)
#pragma unroll
        for (int h = 0; h < 2; h++) {
            const int t = t0 + wm * 64 + i * 16 + h * 8 + ra;
            const float4 r03 = ((const float4*)routing)[(size_t)t * 2];
            const float4 r47 = ((const float4*)routing)[(size_t)t * 2 + 1];
            const float rwv[8] = { r03.x, r03.y, r03.z, r03.w, r47.x, r47.y, r47.z, r47.w };
            float* orow = out + (size_t)t * H_ + h0;
#pragma unroll
            for (int j = 0; j < NF; j++) {
                const int C = wn * WN + j * 8 + ca2;
                float v0 = acc[i][j][2 * h];
                float v1 = acc[i][j][2 * h + 1];
#pragma unroll
                for (int ee = 0; ee < E_; ee++) {
                    v0 += rwv[ee] * sm[ee * BN + C];
                    v1 += rwv[ee] * sm[ee * BN + C + 1];
                }
                *(float2*)(orow + C) = make_float2(v0, v1);
            }
        }
}

// ================= host ====================
extern "C" void kernel_launch(void* const* d_in, const int* in_sizes, int n_in,
                              void* d_out, int out_size) {
    const float *x = nullptr, *rw = nullptr, *w1 = nullptr, *b1 = nullptr,
                *w2 = nullptr, *b2 = nullptr;
    for (int i = 0; i < n_in; i++) {
        const long long s = in_sizes[i];
        const float* p = (const float*)d_in[i];
        if      (s == (long long)T_ * H_)        x  = p;
        else if (s == (long long)T_ * E_)        rw = p;
        else if (s == (long long)E_ * H_ * N2_)  w1 = p;
        else if (s == (long long)E_ * N2_)       b1 = p;
        else if (s == (long long)E_ * D_ * H_)   w2 = p;
        else if (s == (long long)E_ * H_)        b2 = p;
    }
    float* out = (float*)d_out;

    void *p_xr, *p_w1t, *p_w2t;
    cudaGetSymbolAddress(&p_xr,  g_xr);
    cudaGetSymbolAddress(&p_w1t, g_w1t);
    cudaGetSymbolAddress(&p_w2t, g_w2t);

    cudaFuncSetAttribute(k_gemm1, cudaFuncAttributeMaxDynamicSharedMemorySize, SMEM_B);
    cudaFuncSetAttribute(k_gemm2, cudaFuncAttributeMaxDynamicSharedMemorySize, SMEM_B);

    k_round4<<<4096, 256>>>((const float4*)x, (float4*)p_xr, (size_t)T_ * H_ / 4);
    dim3 tb(32, 8);
    k_transpose<<<dim3(N2_ / 32, H_ / 32, E_), tb>>>(w1, (float*)p_w1t, H_, N2_);
    k_transpose<<<dim3(H_ / 32, D_ / 32, E_), tb>>>(w2, (float*)p_w2t, D_, H_);

    k_gemm1<<<dim3(N2_ / BN, T_ / BM, E_), NT, SMEM_B>>>(b1, rw);
    k_gemm2<<<dim3(H_ / BN, T_ / BM), NT, SMEM_B>>>(b2, rw, out);
}

// round 7
// speedup vs baseline: 2.0038x; 1.0602x over previous
#include <cuda_runtime.h>
#include <cstdint>

#define E_  8
#define T_  2048
#define H_  2880
#define D_  2880
#define N2_ 5760

__device__ float g_xr[(size_t)T_ * H_];
__device__ float g_w1t[(size_t)E_ * N2_ * H_];
__device__ float g_w2t[(size_t)E_ * H_ * D_];
__device__ float g_hidden[(size_t)E_ * T_ * D_];

// ---------------- helpers ----------------
__device__ __forceinline__ unsigned smem_u32(const void* p) {
    return (unsigned)__cvta_generic_to_shared(p);
}
__device__ __forceinline__ void cp16(float* s, const float* g) {
    asm volatile("cp.async.cg.shared.global [%0], [%1], 16;" :: "r"(smem_u32(s)), "l"(g));
}
__device__ __forceinline__ void cp_commit() { asm volatile("cp.async.commit_group;"); }
__device__ __forceinline__ void cp_wait1()  { asm volatile("cp.async.wait_group 1;"); }
__device__ __forceinline__ void cp_wait0()  { asm volatile("cp.async.wait_group 0;"); }

__device__ __forceinline__ float tf32r(float x) {
    uint32_t r; asm("cvt.rna.tf32.f32 %0, %1;" : "=r"(r) : "f"(x));
    return __uint_as_float(r);
}
__device__ __forceinline__ void mma8(float* c, const uint32_t* a, const uint32_t* b) {
    asm volatile("mma.sync.aligned.m16n8k8.row.col.f32.tf32.tf32.f32 "
        "{%0,%1,%2,%3}, {%4,%5,%6,%7}, {%8,%9}, {%0,%1,%2,%3};"
        : "+f"(c[0]), "+f"(c[1]), "+f"(c[2]), "+f"(c[3])
        : "r"(a[0]), "r"(a[1]), "r"(a[2]), "r"(a[3]), "r"(b[0]), "r"(b[1]));
}
__device__ __forceinline__ void ldsm4(uint32_t& r0, uint32_t& r1, uint32_t& r2, uint32_t& r3,
                                      uint32_t addr) {
    asm volatile("ldmatrix.sync.aligned.m8n8.x4.shared.b16 {%0,%1,%2,%3}, [%4];"
        : "=r"(r0), "=r"(r1), "=r"(r2), "=r"(r3) : "r"(addr));
}
__device__ __forceinline__ void ldsm2(uint32_t& r0, uint32_t& r1, uint32_t addr) {
    asm volatile("ldmatrix.sync.aligned.m8n8.x2.shared.b16 {%0,%1}, [%2];"
        : "=r"(r0), "=r"(r1) : "r"(addr));
}

// ---------------- tiling ----------------
constexpr int BM = 128, BN = 160, BK = 32;
constexpr int NT = 256;                     // threads (8 warps, grid 2x4)
constexpr int WN = 40, NF = 5;              // per-warp N span, N frags
constexpr int A_FL = BM * 32;               // 4096 floats
constexpr int B_FL = BN * 32;               // 5120 floats
constexpr int STGF = A_FL + B_FL;           // 9216 floats (36 KB)
constexpr int STAGES = 3;
constexpr int SMEM_B = STAGES * STGF * 4;   // 110592 B -> 2 CTAs/SM

// swizzled loads (rows x 32 floats; chunk' = chunk ^ (row&7))
__device__ __forceinline__ void load_A(float* S, const float* G, int lda, int tid) {
#pragma unroll
    for (int i = 0; i < 4; i++) {                    // 1024 chunks / 256 thr
        int c = tid + i * NT;
        int r = c >> 3, q = c & 7;
        cp16(S + r * 32 + (q ^ (r & 7)) * 4, G + (size_t)r * lda + q * 4);
    }
}
__device__ __forceinline__ void load_B(float* S, const float* G, int lda, int tid) {
#pragma unroll
    for (int i = 0; i < 5; i++) {                    // 1280 chunks / 256 thr
        int c = tid + i * NT;
        int r = c >> 3, q = c & 7;
        cp16(S + r * 32 + (q ^ (r & 7)) * 4, G + (size_t)r * lda + q * 4);
    }
}

// per-lane ldmatrix base offsets (bytes)
__device__ __forceinline__ void frag_offsets(uint32_t (&aOff)[4], uint32_t (&bOff)[3],
                                             int wm, int wn, int lane) {
    const int rr = lane & 7, mm = lane >> 3;
#pragma unroll
    for (int i = 0; i < 4; i++) {
        const int row = wm * 64 + i * 16 + (mm & 1) * 8 + rr;
        aOff[i] = row * 128 + ((((mm >> 1) ^ (row & 7)) & 7) << 4);
    }
#pragma unroll
    for (int jp = 0; jp < 2; jp++) {
        const int row = wn * WN + (jp * 2 + (mm >> 1)) * 8 + rr;
        bOff[jp] = row * 128 + ((((mm & 1) ^ (row & 7)) & 7) << 4);
    }
    {
        const int m2 = mm & 1;
        const int row = wn * WN + 32 + rr;
        bOff[2] = row * 128 + (((m2 ^ (row & 7)) & 7) << 4);
    }
}

__device__ __forceinline__ void compute_stage(uint32_t sA, uint32_t sB,
                                              const uint32_t (&aOff)[4],
                                              const uint32_t (&bOff)[3],
                                              float (&acc)[4][NF][4]) {
#pragma unroll
    for (int ks = 0; ks < 4; ks++) {
        const uint32_t kx = ks * 32;
        uint32_t a[4][4], b[NF][2];
#pragma unroll
        for (int i = 0; i < 4; i++)
            ldsm4(a[i][0], a[i][1], a[i][2], a[i][3], sA + (aOff[i] ^ kx));
        ldsm4(b[0][0], b[0][1], b[1][0], b[1][1], sB + (bOff[0] ^ kx));
        ldsm4(b[2][0], b[2][1], b[3][0], b[3][1], sB + (bOff[1] ^ kx));
        ldsm2(b[4][0], b[4][1], sB + (bOff[2] ^ kx));
#pragma unroll
        for (int i = 0; i < 4; i++)
#pragma unroll
            for (int j = 0; j < NF; j++)
                mma8(acc[i][j], a[i], b[j]);
    }
}

// ================= preprocess =================
__global__ void k_round4(const float4* __restrict__ in, float4* __restrict__ out, size_t n4) {
    size_t i = (size_t)blockIdx.x * blockDim.x + threadIdx.x;
    size_t st = (size_t)gridDim.x * blockDim.x;
    for (; i < n4; i += st) {
        float4 v = in[i];
        v.x = tf32r(v.x); v.y = tf32r(v.y); v.z = tf32r(v.z); v.w = tf32r(v.w);
        out[i] = v;
    }
}
__global__ void k_transpose(const float* __restrict__ in, float* __restrict__ out, int R, int C) {
    __shared__ float t[32][33];
    const float* iz = in + (size_t)blockIdx.z * R * C;
    float* oz = out + (size_t)blockIdx.z * R * C;
    int c0 = blockIdx.x * 32, r0 = blockIdx.y * 32;
#pragma unroll
    for (int i = 0; i < 32; i += 8)
        t[threadIdx.y + i][threadIdx.x] = iz[(size_t)(r0 + threadIdx.y + i) * C + c0 + threadIdx.x];
    __syncthreads();
#pragma unroll
    for (int i = 0; i < 32; i += 8)
        oz[(size_t)(c0 + threadIdx.y + i) * R + r0 + threadIdx.x] = tf32r(t[threadIdx.x][threadIdx.y + i]);
}

// ================= GEMM1 =================
__global__ void __launch_bounds__(NT, 2)
k_gemm1(const float* __restrict__ b1, const float* __restrict__ routing) {
    extern __shared__ __align__(128) float sm[];
    const int tid = threadIdx.x, lane = tid & 31, warp = tid >> 5;
    const int wm = warp & 1, wn = warp >> 1;
    const int n0 = blockIdx.x * BN;
    const int t0 = blockIdx.y * BM;
    const int e  = blockIdx.z;

    const uint32_t sb = smem_u32(sm);
    const float* Ag = g_xr + (size_t)t0 * H_;
    const float* Bg = g_w1t + ((size_t)e * N2_ + n0) * H_;

    uint32_t aOff[4], bOff[3];
    frag_offsets(aOff, bOff, wm, wn, lane);

    float acc[4][NF][4];
#pragma unroll
    for (int i = 0; i < 4; i++)
#pragma unroll
        for (int j = 0; j < NF; j++)
#pragma unroll
            for (int q = 0; q < 4; q++) acc[i][j][q] = 0.f;

    constexpr int KT = H_ / BK;   // 90
#pragma unroll
    for (int s = 0; s < 2; s++) {
        load_A(sm + s * STGF, Ag + s * BK, H_, tid);
        load_B(sm + s * STGF + A_FL, Bg + s * BK, H_, tid);
        cp_commit();
    }

    for (int kt = 0; kt < KT; kt++) {
        if (kt < KT - 1) cp_wait1(); else cp_wait0();
        __syncthreads();
        const int nk = kt + 2;
        if (nk < KT) {                         // issue loads FIRST, then compute
            const int ns = nk % 3;
            load_A(sm + ns * STGF, Ag + nk * BK, H_, tid);
            load_B(sm + ns * STGF + A_FL, Bg + nk * BK, H_, tid);
            cp_commit();
        }
        const int s = kt % 3;
        compute_stage(sb + s * STGF * 4, sb + (s * STGF + A_FL) * 4, aOff, bOff, acc);
    }

    __syncthreads();
    if (tid < BN) sm[tid] = b1[(size_t)e * N2_ + n0 + tid];
    __syncthreads();

    const int ra = lane >> 2, ca2 = 2 * (lane & 3);
#pragma unroll
    for (int i = 0; i < 4; i++)
#pragma unroll
        for (int h = 0; h < 2; h++) {
            const int row = wm * 64 + i * 16 + h * 8 + ra;
            const float rw = routing[(size_t)(t0 + row) * E_ + e];
            float* gh = g_hidden + ((size_t)e * T_ + t0 + row) * D_ + (n0 >> 1);
#pragma unroll
            for (int j = 0; j < NF; j++) {
                const int C = wn * WN + j * 8 + ca2;
                float gate = acc[i][j][2 * h]     + sm[C];
                float up   = acc[i][j][2 * h + 1] + sm[C + 1];
                gate = fminf(gate, 7.0f);
                up   = fminf(fmaxf(up, -7.0f), 7.0f);
                const float glu = gate / (1.0f + __expf(-1.702f * gate));
                gh[C >> 1] = tf32r((up + 1.0f) * glu * rw);
            }
        }
}

// ================= GEMM2 =================
__global__ void __launch_bounds__(NT, 2)
k_gemm2(const float* __restrict__ b2, const float* __restrict__ routing,
        float* __restrict__ out) {
    extern __shared__ __align__(128) float sm[];
    const int tid = threadIdx.x, lane = tid & 31, warp = tid >> 5;
    const int wm = warp & 1, wn = warp >> 1;
    const int h0 = blockIdx.x * BN;
    const int t0 = blockIdx.y * BM;

    const uint32_t sb = smem_u32(sm);
    uint32_t aOff[4], bOff[3];
    frag_offsets(aOff, bOff, wm, wn, lane);

    float acc[4][NF][4];
#pragma unroll
    for (int i = 0; i < 4; i++)
#pragma unroll
        for (int j = 0; j < NF; j++)
#pragma unroll
            for (int q = 0; q < 4; q++) acc[i][j][q] = 0.f;

    constexpr int KPE = D_ / BK;   // 90
    constexpr int KT  = E_ * KPE;  // 720

#pragma unroll
    for (int s = 0; s < 2; s++) {
        load_A(sm + s * STGF, g_hidden + (size_t)t0 * D_ + s * BK, D_, tid);
        load_B(sm + s * STGF + A_FL, g_w2t + (size_t)h0 * D_ + s * BK, D_, tid);
        cp_commit();
    }

    int ez = 0, kk = 2;            // next (e, k-chunk) to load
    for (int kt = 0; kt < KT; kt++) {
        if (kt < KT - 1) cp_wait1(); else cp_wait0();
        __syncthreads();
        const int nk = kt + 2;
        if (nk < KT) {
            const int ns = nk % 3;
            load_A(sm + ns * STGF, g_hidden + ((size_t)ez * T_ + t0) * D_ + kk * BK, D_, tid);
            load_B(sm + ns * STGF + A_FL, g_w2t + ((size_t)ez * H_ + h0) * D_ + kk * BK, D_, tid);
            cp_commit();
            if (++kk == KPE) { kk = 0; ez++; }
        }
        const int s = kt % 3;
        compute_stage(sb + s * STGF * 4, sb + (s * STGF + A_FL) * 4, aOff, bOff, acc);
    }

    __syncthreads();
    for (int i = tid; i < E_ * BN; i += NT) {
        const int ee = i / BN, c = i - ee * BN;
        sm[i] = b2[(size_t)ee * H_ + h0 + c];
    }
    __syncthreads();

    const int ra = lane >> 2, ca2 = 2 * (lane & 3);
#pragma unroll
    for (int i = 0; i < 4; i++)
#pragma unroll
        for (int h = 0; h < 2; h++) {
            const int t = t0 + wm * 64 + i * 16 + h * 8 + ra;
            const float4 r03 = ((const float4*)routing)[(size_t)t * 2];
            const float4 r47 = ((const float4*)routing)[(size_t)t * 2 + 1];
            const float rwv[8] = { r03.x, r03.y, r03.z, r03.w, r47.x, r47.y, r47.z, r47.w };
            float* orow = out + (size_t)t * H_ + h0;
#pragma unroll
            for (int j = 0; j < NF; j++) {
                const int C = wn * WN + j * 8 + ca2;
                float v0 = acc[i][j][2 * h];
                float v1 = acc[i][j][2 * h + 1];
#pragma unroll
                for (int ee = 0; ee < E_; ee++) {
                    v0 += rwv[ee] * sm[ee * BN + C];
                    v1 += rwv[ee] * sm[ee * BN + C + 1];
                }
                *(float2*)(orow + C) = make_float2(v0, v1);
            }
        }
}

// ================= host ====================
extern "C" void kernel_launch(void* const* d_in, const int* in_sizes, int n_in,
                              void* d_out, int out_size) {
    const float *x = nullptr, *rw = nullptr, *w1 = nullptr, *b1 = nullptr,
                *w2 = nullptr, *b2 = nullptr;
    for (int i = 0; i < n_in; i++) {
        const long long s = in_sizes[i];
        const float* p = (const float*)d_in[i];
        if      (s == (long long)T_ * H_)        x  = p;
        else if (s == (long long)T_ * E_)        rw = p;
        else if (s == (long long)E_ * H_ * N2_)  w1 = p;
        else if (s == (long long)E_ * N2_)       b1 = p;
        else if (s == (long long)E_ * D_ * H_)   w2 = p;
        else if (s == (long long)E_ * H_)        b2 = p;
    }
    float* out = (float*)d_out;

    void *p_xr, *p_w1t, *p_w2t;
    cudaGetSymbolAddress(&p_xr,  g_xr);
    cudaGetSymbolAddress(&p_w1t, g_w1t);
    cudaGetSymbolAddress(&p_w2t, g_w2t);

    cudaFuncSetAttribute(k_gemm1, cudaFuncAttributeMaxDynamicSharedMemorySize, SMEM_B);
    cudaFuncSetAttribute(k_gemm2, cudaFuncAttributeMaxDynamicSharedMemorySize, SMEM_B);

    k_round4<<<4096, 256>>>((const float4*)x, (float4*)p_xr, (size_t)T_ * H_ / 4);
    dim3 tb(32, 8);
    k_transpose<<<dim3(N2_ / 32, H_ / 32, E_), tb>>>(w1, (float*)p_w1t, H_, N2_);
    k_transpose<<<dim3(H_ / 32, D_ / 32, E_), tb>>>(w2, (float*)p_w2t, D_, H_);

    k_gemm1<<<dim3(N2_ / BN, T_ / BM, E_), NT, SMEM_B>>>(b1, rw);
    k_gemm2<<<dim3(H_ / BN, T_ / BM), NT, SMEM_B>>>(b2, rw, out);
}